// round 2
// baseline (speedup 1.0000x reference)
#include <cuda_runtime.h>
#include <cstdint>

// Problem constants (HQQGroupedGemm_37357625540844)
#define E_   8
#define T_   2048
#define IN_  2048
#define OUT_ 2048
#define GS_  64

// Tiling
#define BM 128
#define BN 128
#define BK 32
#define NTHREADS 256
#define KSTEPS (IN_ / BK)      // 64
#define AS_STRIDE 36           // 32 + 4 pad (floats), 16B-aligned rows, conflict-free frags
#define BS_STRIDE 136          // 128 + 8 pad (floats), conflict-free B frags
#define SMEM_BYTES ((2 * BM * AS_STRIDE + 2 * BK * BS_STRIDE) * 4)  // 71680

__device__ __forceinline__ unsigned f2tf(float f) {
    unsigned u;
    asm("cvt.rna.tf32.f32 %0, %1;" : "=r"(u) : "f"(f));
    return u;
}

__device__ __forceinline__ void mma_tf32(float* c, const unsigned* a, const unsigned* b) {
    asm volatile(
        "mma.sync.aligned.m16n8k8.row.col.f32.tf32.tf32.f32 "
        "{%0,%1,%2,%3}, {%4,%5,%6,%7}, {%8,%9}, {%0,%1,%2,%3};"
        : "+f"(c[0]), "+f"(c[1]), "+f"(c[2]), "+f"(c[3])
        : "r"(a[0]), "r"(a[1]), "r"(a[2]), "r"(a[3]), "r"(b[0]), "r"(b[1]));
}

__device__ __forceinline__ void cpasync16(float* s, const float* g) {
    unsigned saddr = (unsigned)__cvta_generic_to_shared(s);
    asm volatile("cp.async.cg.shared.global [%0], [%1], 16;" :: "r"(saddr), "l"(g));
}
__device__ __forceinline__ void cpcommit() { asm volatile("cp.async.commit_group;"); }
__device__ __forceinline__ void cpwait0()  { asm volatile("cp.async.wait_group 0;" ::: "memory"); }

extern __shared__ float smem[];

__global__ void __launch_bounds__(NTHREADS)
hqq_grouped_gemm_kernel(const float* __restrict__ x,
                        const int*   __restrict__ qw,
                        const float* __restrict__ sz,
                        const int*   __restrict__ tpe,
                        float*       __restrict__ out)
{
    const int e  = blockIdx.z;
    const int mb = blockIdx.y;
    const int nb = blockIdx.x;

    // Expert row range from tokens_per_expert prefix sum
    int cnt[E_];
#pragma unroll
    for (int i = 0; i < E_; i++) cnt[i] = __ldg(&tpe[i]);
    int r0 = 0;
#pragma unroll
    for (int i = 0; i < E_; i++) if (i < e) r0 += cnt[i];
    const int r1  = r0 + cnt[e];
    const int mlo = max(r0, mb * BM);
    const int mhi = min(r1, mb * BM + BM);
    if (mlo >= mhi) return;   // uniform per block

    float* As = smem;                            // [2][BM][AS_STRIDE]
    float* Bs = smem + 2 * BM * AS_STRIDE;       // [2][BK][BS_STRIDE]

    const int tid  = threadIdx.x;
    const int warp = tid >> 5, lane = tid & 31;
    const int wm   = warp >> 1, wn = warp & 1;   // 4 x 2 warp grid (32x64 warp tile)
    const int gid  = lane >> 2, tig = lane & 3;

    // B dequant mapping: thread handles 4 rows x 4 cols
    const int cg   = tid & 31;           // column group (4 consecutive n)
    const int rb   = (tid >> 5) * 4;     // row base within k-tile
    const int ncol = nb * BN + cg * 4;

    const int* qp = qw + (size_t)e * IN_ * OUT_ + (size_t)rb * OUT_ + ncol;
    const float* szp = sz + (size_t)e * (IN_ / GS_) * (OUT_ * 2) + (size_t)ncol * 2;

    // ---- pipeline helpers -------------------------------------------------
    auto loadA = [&](int i, float* dst) {
        const int k0 = i * BK;
#pragma unroll
        for (int j = 0; j < 4; j++) {
            int c = j * NTHREADS + tid;
            int row = c >> 3, kc = c & 7;
            cpasync16(dst + row * AS_STRIDE + kc * 4,
                      x + (size_t)(mb * BM + row) * IN_ + k0 + kc * 4);
        }
    };

    auto loadQ = [&](int i, int4* qv) {
        const int k0 = i * BK;
#pragma unroll
        for (int j = 0; j < 4; j++)
            qv[j] = *reinterpret_cast<const int4*>(qp + (size_t)(k0 + j) * OUT_);
    };

    auto loadSZ = [&](int g, float4& a, float4& b) {
        a = *reinterpret_cast<const float4*>(szp + (size_t)g * (OUT_ * 2));
        b = *reinterpret_cast<const float4*>(szp + (size_t)g * (OUT_ * 2) + 4);
    };

    auto dequant = [&](const int4* qv, float* dst, float4 sza, float4 szb) {
#pragma unroll
        for (int j = 0; j < 4; j++) {
            float w0 = (float)(qv[j].x - 8) * sza.x + sza.y;
            float w1 = (float)(qv[j].y - 8) * sza.z + sza.w;
            float w2 = (float)(qv[j].z - 8) * szb.x + szb.y;
            float w3 = (float)(qv[j].w - 8) * szb.z + szb.w;
            uint4 wv;
            wv.x = f2tf(w0); wv.y = f2tf(w1); wv.z = f2tf(w2); wv.w = f2tf(w3);
            *reinterpret_cast<uint4*>(dst + (rb + j) * BS_STRIDE + cg * 4) = wv;
        }
    };

    float acc[2][8][4];
#pragma unroll
    for (int mt = 0; mt < 2; mt++)
#pragma unroll
        for (int nt = 0; nt < 8; nt++)
#pragma unroll
            for (int q = 0; q < 4; q++) acc[mt][nt][q] = 0.0f;

    auto domma = [&](const float* AsC, const float* BsC) {
#pragma unroll
        for (int ksub = 0; ksub < 4; ksub++) {
            const int kk = ksub * 8 + tig;
            unsigned a[2][4];
#pragma unroll
            for (int mt = 0; mt < 2; mt++) {
                int r = wm * 32 + mt * 16 + gid;
                a[mt][0] = f2tf(AsC[(r)     * AS_STRIDE + kk]);
                a[mt][1] = f2tf(AsC[(r + 8) * AS_STRIDE + kk]);
                a[mt][2] = f2tf(AsC[(r)     * AS_STRIDE + kk + 4]);
                a[mt][3] = f2tf(AsC[(r + 8) * AS_STRIDE + kk + 4]);
            }
#pragma unroll
            for (int nt = 0; nt < 8; nt++) {
                int cc = wn * 64 + nt * 8 + gid;
                unsigned b[2];
                b[0] = __float_as_uint(BsC[(kk)     * BS_STRIDE + cc]);
                b[1] = __float_as_uint(BsC[(kk + 4) * BS_STRIDE + cc]);
                mma_tf32(acc[0][nt], a[0], b);
                mma_tf32(acc[1][nt], a[1], b);
            }
        }
    };

    // ---- prologue ---------------------------------------------------------
    int4 qv[4];
    float4 sza, szb;
    loadA(0, As);
    cpcommit();
    loadQ(0, qv);
    loadSZ(0, sza, szb);
    dequant(qv, Bs, sza, szb);
    cpwait0();
    __syncthreads();

    // ---- main loop (double-buffered) --------------------------------------
#pragma unroll 1
    for (int i = 0; i < KSTEPS; i++) {
        float* AsC = As + (i & 1) * (BM * AS_STRIDE);
        float* BsC = Bs + (i & 1) * (BK * BS_STRIDE);
        float* AsN = As + ((i + 1) & 1) * (BM * AS_STRIDE);
        float* BsN = Bs + ((i + 1) & 1) * (BK * BS_STRIDE);

        const bool hasNext = (i + 1 < KSTEPS);
        if (hasNext) {
            loadA(i + 1, AsN);
            cpcommit();
            loadQ(i + 1, qv);
            if (((i + 1) & 1) == 0) loadSZ((i + 1) >> 1, sza, szb);  // group = i>>1
        }

        domma(AsC, BsC);

        if (hasNext) {
            dequant(qv, BsN, sza, szb);
            cpwait0();
        }
        __syncthreads();
    }

    // ---- epilogue: masked store (only rows belonging to this expert) ------
#pragma unroll
    for (int mt = 0; mt < 2; mt++) {
#pragma unroll
        for (int nt = 0; nt < 8; nt++) {
            int row0 = mb * BM + wm * 32 + mt * 16 + gid;
            int col  = nb * BN + wn * 64 + nt * 8 + tig * 2;
            if (row0 >= mlo && row0 < mhi) {
                float2 v = make_float2(acc[mt][nt][0], acc[mt][nt][1]);
                *reinterpret_cast<float2*>(out + (size_t)row0 * OUT_ + col) = v;
            }
            int row1 = row0 + 8;
            if (row1 >= mlo && row1 < mhi) {
                float2 v = make_float2(acc[mt][nt][2], acc[mt][nt][3]);
                *reinterpret_cast<float2*>(out + (size_t)row1 * OUT_ + col) = v;
            }
        }
    }
}

extern "C" void kernel_launch(void* const* d_in, const int* in_sizes, int n_in,
                              void* d_out, int out_size) {
    (void)in_sizes; (void)n_in; (void)out_size;
    const float* x   = (const float*)d_in[0];
    const int*   qw  = (const int*)d_in[1];
    const float* sz  = (const float*)d_in[2];
    const int*   tpe = (const int*)d_in[3];
    float*       out = (float*)d_out;

    cudaFuncSetAttribute(hqq_grouped_gemm_kernel,
                         cudaFuncAttributeMaxDynamicSharedMemorySize, SMEM_BYTES);

    dim3 grid(OUT_ / BN, T_ / BM, E_);
    hqq_grouped_gemm_kernel<<<grid, NTHREADS, SMEM_BYTES>>>(x, qw, sz, tpe, out);
}